// round 14
// baseline (speedup 1.0000x reference)
#include <cuda_runtime.h>
#include <cuda_fp16.h>
#include <math.h>

// Problem constants
#define H        128          // hidden dim
#define NPTS     1024         // points (B=1)
#define MQ       256          // m-range per block (quarter row)
#define NBLK     (NPTS * 4)   // 4096 blocks: (n, m-quarter)

// Table: g_o(d) on d in [0,64) step 1/32, first-order Taylor per node.
// Realizable d = dist/0.2 stays < ~55 for N(0,1)^3 points; k clamped anyway.
#define NODES    2048
#define DELTA    0.03125f
#define INV_DELTA 32.0f
#define NPB      8            // nodes per block in table build

// -ln(10000)/64
#define FREQ_DECAY (-0.14391156864f)

__device__ __align__(16) __half2 g_T[NODES][H];   // (g0, g1) per (node, o)

// ---------------------------------------------------------------------------
// Table build (R11 version — measured-best prologue, untouched).
// 256 blocks x 256 threads; o = tid & 127, half = tid >> 7.
//   g0[k][o] = b[o] + sum_j W[o,2j] sin(q f_j) + W[o,2j+1] cos(q f_j)
//   g1[k][o] =        sum_j f_j (W[o,2j] cos(q f_j) - W[o,2j+1] sin(q f_j))
// ---------------------------------------------------------------------------
__global__ void __launch_bounds__(256)
build_table_kernel(const float* __restrict__ W, const float* __restrict__ b) {
    __shared__ float sSin[NPB][64];
    __shared__ float sCos[NPB][64];
    __shared__ float sF[64];
    __shared__ float sR0[NPB][H];
    __shared__ float sR1[NPB][H];

    const int tid   = threadIdx.x;
    const int o     = tid & (H - 1);
    const int half  = tid >> 7;
    const int node0 = blockIdx.x * NPB;

    if (tid < 64) sF[tid] = expf(FREQ_DECAY * (float)tid);

#pragma unroll
    for (int e = tid; e < NPB * 64; e += 256) {
        int ni = e >> 6;
        int j  = e & 63;
        float q = (float)(node0 + ni) * DELTA;
        float f = expf(FREQ_DECAY * (float)j);
        float s, c;
        sincosf(q * f, &s, &c);
        sSin[ni][j] = s;
        sCos[ni][j] = c;
    }

    float4 wreg[16];
    {
        const float4* wrow =
            reinterpret_cast<const float4*>(W + (size_t)o * H + 64 * half);
#pragma unroll
        for (int i = 0; i < 16; i++) wreg[i] = wrow[i];
    }

    float g0[NPB], g1[NPB];
    const float binit = (half == 0) ? b[o] : 0.0f;
#pragma unroll
    for (int ni = 0; ni < NPB; ni++) { g0[ni] = binit; g1[ni] = 0.0f; }

    __syncthreads();

#pragma unroll
    for (int ni = 0; ni < NPB; ni++) {
#pragma unroll
        for (int i = 0; i < 16; i++) {
            int j0 = 32 * half + 2 * i;
            float s0 = sSin[ni][j0],     c0 = sCos[ni][j0];
            float s1 = sSin[ni][j0 + 1], c1 = sCos[ni][j0 + 1];
            float4 w = wreg[i];
            g0[ni] = fmaf(w.x, s0, g0[ni]);
            g0[ni] = fmaf(w.y, c0, g0[ni]);
            g0[ni] = fmaf(w.z, s1, g0[ni]);
            g0[ni] = fmaf(w.w, c1, g0[ni]);
            g1[ni] = fmaf(sF[j0],     fmaf(w.x, c0, -w.y * s0), g1[ni]);
            g1[ni] = fmaf(sF[j0 + 1], fmaf(w.z, c1, -w.w * s1), g1[ni]);
        }
    }

    if (half == 1) {
#pragma unroll
        for (int ni = 0; ni < NPB; ni++) {
            sR0[ni][o] = g0[ni];
            sR1[ni][o] = g1[ni];
        }
    }
    __syncthreads();
    if (half == 0) {
#pragma unroll
        for (int ni = 0; ni < NPB; ni++) {
            int node = node0 + ni;
            if (node < NODES) {
                float a0 = g0[ni] + sR0[ni][o];
                float a1 = g1[ni] + sR1[ni][o];
                g_T[node][o] =
                    __halves2half2(__float2half_rn(a0), __float2half_rn(a1));
            }
        }
    }
}

// ---------------------------------------------------------------------------
// Main kernel, CONTIGUOUS-BLOCK-FOOTPRINT remap.
// Grid = 1024 n-rows x 4 m-quarters = 4096 blocks of 256 threads.
// bid>>2 = n, bid&3 = mb. Phase A: thread t computes pair (n, mb*256+t) ->
// (k, delta) in smem. Phase B: warp w streams m = mb*256 + 32w .. +31: per m
// a broadcast LDS, one uint4 table load (512 B/warp, L2-hot), 4 FMAs, one
// streaming STG.128. The 8 warps cover ONE contiguous 128 KB region (vs 8
// disjoint 16 KB chunks at 512 KB stride before), and 4 consecutive bids
// cover a full contiguous 512 KB n-row -> maximal DRAM row-buffer locality.
// ---------------------------------------------------------------------------
__global__ void __launch_bounds__(256)
geo_emb_kernel(const float* __restrict__ pts, float* __restrict__ out) {
    __shared__ int   sk[256];
    __shared__ float sd[256];

    const int tid = threadIdx.x;
    const int n   = blockIdx.x >> 2;       // 0..1023
    const int mb  = blockIdx.x & 3;        // m-quarter

    // Phase A: one unique pair (n, m) per thread -> (k, delta) in smem.
    {
        const int m = mb * MQ + tid;
        float dx = pts[n * 3 + 0] - pts[m * 3 + 0];
        float dy = pts[n * 3 + 1] - pts[m * 3 + 1];
        float dz = pts[n * 3 + 2] - pts[m * 3 + 2];
        float d  = sqrtf(fmaf(dx, dx, fmaf(dy, dy, dz * dz))) * 5.0f;
        int k = __float2int_rn(d * INV_DELTA);
        k = min(k, NODES - 1);
        sk[tid] = k;
        sd[tid] = fmaf((float)k, -DELTA, d);   // in [-DELTA/2, DELTA/2]
    }
    __syncthreads();

    // Phase B: warp w streams its 32 consecutive m's; block footprint is one
    // contiguous 128 KB range of the output.
    const int w    = tid >> 5;
    const int lane = tid & 31;
    float* rowW =
        out + ((size_t)n * NPTS + (size_t)mb * MQ + 32 * w) * H + 4 * lane;

#pragma unroll 8
    for (int ml = 0; ml < 32; ml++) {
        int   k     = sk[w * 32 + ml];     // broadcast LDS (no conflicts)
        float delta = sd[w * 32 + ml];

        const uint4 t = *(reinterpret_cast<const uint4*>(&g_T[k][0]) + lane);
        float2 p0 = __half22float2(*reinterpret_cast<const __half2*>(&t.x));
        float2 p1 = __half22float2(*reinterpret_cast<const __half2*>(&t.y));
        float2 p2 = __half22float2(*reinterpret_cast<const __half2*>(&t.z));
        float2 p3 = __half22float2(*reinterpret_cast<const __half2*>(&t.w));

        float4 rr;
        rr.x = fmaf(delta, p0.y, p0.x);
        rr.y = fmaf(delta, p1.y, p1.x);
        rr.z = fmaf(delta, p2.y, p2.x);
        rr.w = fmaf(delta, p3.y, p3.x);

        __stcs(reinterpret_cast<float4*>(rowW + (size_t)ml * H), rr);
    }
}

// ---------------------------------------------------------------------------
// Inputs: points (1,1024,3) f32, W (128,128) f32, b (128,) f32.
// Output: (1,1024,1024,128) f32.
// ---------------------------------------------------------------------------
extern "C" void kernel_launch(void* const* d_in, const int* in_sizes, int n_in,
                              void* d_out, int out_size) {
    const float* pts = (const float*)d_in[0];
    const float* W   = (const float*)d_in[1];
    const float* b   = (const float*)d_in[2];
    float* out       = (float*)d_out;

    build_table_kernel<<<NODES / NPB, 256>>>(W, b);
    geo_emb_kernel<<<NBLK, 256>>>(pts, out);
}

// round 15
// speedup vs baseline: 1.4775x; 1.4775x over previous
#include <cuda_runtime.h>
#include <cuda_fp16.h>
#include <math.h>

// Problem constants
#define H        128          // hidden dim
#define NPTS     1024         // points (B=1)
#define TILE     32           // m-tile edge
#define NTILES   (NPTS / TILE)     // 32
#define GRPS     4                 // row-groups per (n-tile, m-tile) pair
#define RROWS    (TILE / GRPS)     // 8 n-rows per block (one per warp)
#define NBLK     (NTILES * NTILES * GRPS)   // 4096

// Table: g_o(d) on d in [0,64) step 1/32, first-order Taylor per node.
// Realizable d = dist/0.2 stays < ~55 for N(0,1)^3 points; k clamped anyway.
#define NODES    2048
#define DELTA    0.03125f
#define INV_DELTA 32.0f
#define NPB      8            // nodes per block in table build

// -ln(10000)/64
#define FREQ_DECAY (-0.14391156864f)

__device__ __align__(16) __half2 g_T[NODES][H];   // (g0, g1) per (node, o)

// ---------------------------------------------------------------------------
// Table build (measured-best prologue). 256 blocks x 256 threads;
// o = tid & 127, half = tid >> 7 (j range 32*half..+31). W row segment in
// registers (16 x LDG.128); halves combined via smem.
//   g0[k][o] = b[o] + sum_j W[o,2j] sin(q f_j) + W[o,2j+1] cos(q f_j)
//   g1[k][o] =        sum_j f_j (W[o,2j] cos(q f_j) - W[o,2j+1] sin(q f_j))
// with q = k*DELTA, f_j = exp(FREQ_DECAY*j).
// ---------------------------------------------------------------------------
__global__ void __launch_bounds__(256)
build_table_kernel(const float* __restrict__ W, const float* __restrict__ b) {
    __shared__ float sSin[NPB][64];
    __shared__ float sCos[NPB][64];
    __shared__ float sF[64];
    __shared__ float sR0[NPB][H];
    __shared__ float sR1[NPB][H];

    const int tid   = threadIdx.x;
    const int o     = tid & (H - 1);
    const int half  = tid >> 7;
    const int node0 = blockIdx.x * NPB;

    if (tid < 64) sF[tid] = expf(FREQ_DECAY * (float)tid);

#pragma unroll
    for (int e = tid; e < NPB * 64; e += 256) {
        int ni = e >> 6;
        int j  = e & 63;
        float q = (float)(node0 + ni) * DELTA;
        float f = expf(FREQ_DECAY * (float)j);
        float s, c;
        sincosf(q * f, &s, &c);
        sSin[ni][j] = s;
        sCos[ni][j] = c;
    }

    float4 wreg[16];
    {
        const float4* wrow =
            reinterpret_cast<const float4*>(W + (size_t)o * H + 64 * half);
#pragma unroll
        for (int i = 0; i < 16; i++) wreg[i] = wrow[i];
    }

    float g0[NPB], g1[NPB];
    const float binit = (half == 0) ? b[o] : 0.0f;
#pragma unroll
    for (int ni = 0; ni < NPB; ni++) { g0[ni] = binit; g1[ni] = 0.0f; }

    __syncthreads();

#pragma unroll
    for (int ni = 0; ni < NPB; ni++) {
#pragma unroll
        for (int i = 0; i < 16; i++) {
            int j0 = 32 * half + 2 * i;
            float s0 = sSin[ni][j0],     c0 = sCos[ni][j0];
            float s1 = sSin[ni][j0 + 1], c1 = sCos[ni][j0 + 1];
            float4 w = wreg[i];
            g0[ni] = fmaf(w.x, s0, g0[ni]);
            g0[ni] = fmaf(w.y, c0, g0[ni]);
            g0[ni] = fmaf(w.z, s1, g0[ni]);
            g0[ni] = fmaf(w.w, c1, g0[ni]);
            g1[ni] = fmaf(sF[j0],     fmaf(w.x, c0, -w.y * s0), g1[ni]);
            g1[ni] = fmaf(sF[j0 + 1], fmaf(w.z, c1, -w.w * s1), g1[ni]);
        }
    }

    if (half == 1) {
#pragma unroll
        for (int ni = 0; ni < NPB; ni++) {
            sR0[ni][o] = g0[ni];
            sR1[ni][o] = g1[ni];
        }
    }
    __syncthreads();
    if (half == 0) {
#pragma unroll
        for (int ni = 0; ni < NPB; ni++) {
            int node = node0 + ni;
            if (node < NODES) {
                float a0 = g0[ni] + sR0[ni][o];
                float a1 = g1[ni] + sR1[ni][o];
                g_T[node][o] =
                    __halves2half2(__float2half_rn(a0), __float2half_rn(a1));
            }
        }
    }
}

// ---------------------------------------------------------------------------
// Main kernel (measured-best): tile-blocked, all-sequential stores, k/delta
// dedup. Grid = 32x32 tile-pairs x 4 row-groups = 4096 blocks of 256 threads.
// The (n-tile x m-tile) blocking is load-bearing: all 8 warps iterate the
// SAME 32-point m-tile, so table lines for the block's k-values are heavily
// reused in L1 (the R14 contiguous-footprint remap broke this and regressed
// 78 -> 117 us).
// Phase A: one unique (n-row, m) pair per thread -> (k, delta) in smem.
// Phase B: warp w streams n-row grp*8+w against the m-tile: per m a broadcast
// LDS, one uint4 table load (512 B/warp, L2-hot), 4 FMAs, one streaming
// STG.128 -> every warp writes a 16 KB fully sequential run.
// ---------------------------------------------------------------------------
__global__ void __launch_bounds__(256)
geo_emb_kernel(const float* __restrict__ pts, float* __restrict__ out) {
    __shared__ int   sk[256];
    __shared__ float sd[256];

    const int tid  = threadIdx.x;
    const int pair = blockIdx.x >> 2;     // 0..1023: (ti, tj) ordered
    const int grp  = blockIdx.x & 3;
    const int ti   = pair >> 5;
    const int tj   = pair & 31;

    // Phase A: one unique pair per thread -> (k, delta) in smem.
    {
        const int nl = tid >> 5;          // 0..7
        const int ml = tid & 31;
        const int n  = ti * TILE + grp * RROWS + nl;
        const int m  = tj * TILE + ml;
        float dx = pts[n * 3 + 0] - pts[m * 3 + 0];
        float dy = pts[n * 3 + 1] - pts[m * 3 + 1];
        float dz = pts[n * 3 + 2] - pts[m * 3 + 2];
        float d  = sqrtf(fmaf(dx, dx, fmaf(dy, dy, dz * dz))) * 5.0f;
        int k = __float2int_rn(d * INV_DELTA);
        k = min(k, NODES - 1);
        sk[tid] = k;
        sd[tid] = fmaf((float)k, -DELTA, d);   // in [-DELTA/2, DELTA/2]
    }
    __syncthreads();

    // Phase B: stream one n-row per warp, all stores sequential.
    const int w    = tid >> 5;
    const int lane = tid & 31;
    const int n    = ti * TILE + grp * RROWS + w;
    float* rowN = out + ((size_t)n * NPTS + (size_t)tj * TILE) * H + 4 * lane;

#pragma unroll 8
    for (int ml = 0; ml < TILE; ml++) {
        int   k     = sk[w * 32 + ml];    // broadcast LDS (no conflicts)
        float delta = sd[w * 32 + ml];

        const uint4 t = *(reinterpret_cast<const uint4*>(&g_T[k][0]) + lane);
        float2 p0 = __half22float2(*reinterpret_cast<const __half2*>(&t.x));
        float2 p1 = __half22float2(*reinterpret_cast<const __half2*>(&t.y));
        float2 p2 = __half22float2(*reinterpret_cast<const __half2*>(&t.z));
        float2 p3 = __half22float2(*reinterpret_cast<const __half2*>(&t.w));

        float4 rr;
        rr.x = fmaf(delta, p0.y, p0.x);
        rr.y = fmaf(delta, p1.y, p1.x);
        rr.z = fmaf(delta, p2.y, p2.x);
        rr.w = fmaf(delta, p3.y, p3.x);

        __stcs(reinterpret_cast<float4*>(rowN + (size_t)ml * H), rr);
    }
}

// ---------------------------------------------------------------------------
// Inputs: points (1,1024,3) f32, W (128,128) f32, b (128,) f32.
// Output: (1,1024,1024,128) f32.
// ---------------------------------------------------------------------------
extern "C" void kernel_launch(void* const* d_in, const int* in_sizes, int n_in,
                              void* d_out, int out_size) {
    const float* pts = (const float*)d_in[0];
    const float* W   = (const float*)d_in[1];
    const float* b   = (const float*)d_in[2];
    float* out       = (float*)d_out;

    build_table_kernel<<<NODES / NPB, 256>>>(W, b);
    geo_emb_kernel<<<NBLK, 256>>>(pts, out);
}

// round 16
// speedup vs baseline: 1.5518x; 1.0503x over previous
#include <cuda_runtime.h>
#include <cuda_fp16.h>
#include <math.h>

// Problem constants
#define H        128          // hidden dim
#define NPTS     1024         // points (B=1)
#define TILE     32           // m-tile edge
#define NTILES   (NPTS / TILE)     // 32
#define GRPS     4                 // row-groups per (n-tile, m-tile) pair
#define RROWS    (TILE / GRPS)     // 8 n-rows per block (one per warp)
#define NBLK     (NTILES * NTILES * GRPS)   // 4096

// Table: g_o(d) on d in [0,64) step 1/16, first-order Taylor per node.
// Error budget: Taylor remainder at DELTA=1/16 is ~6e-5 abs worst-case,
// ~3x below the fp16-G0 quantization term (~2.1e-4) that dominates rel_err.
// Realizable d = dist/0.2 stays < ~55 for N(0,1)^3 points; k clamped anyway.
#define NODES    1024
#define DELTA    0.0625f
#define INV_DELTA 16.0f
#define NPB      8            // nodes per block in table build -> 128 blocks

// -ln(10000)/64
#define FREQ_DECAY (-0.14391156864f)

__device__ __align__(16) __half2 g_T[NODES][H];   // (g0, g1) per (node, o)

// ---------------------------------------------------------------------------
// Table build (measured-best structure; half the nodes of R15).
// 128 blocks x 256 threads — one balanced single wave.
// o = tid & 127, half = tid >> 7 (j range 32*half..+31). W row segment in
// registers (16 x LDG.128); halves combined via smem.
//   g0[k][o] = b[o] + sum_j W[o,2j] sin(q f_j) + W[o,2j+1] cos(q f_j)
//   g1[k][o] =        sum_j f_j (W[o,2j] cos(q f_j) - W[o,2j+1] sin(q f_j))
// with q = k*DELTA, f_j = exp(FREQ_DECAY*j).
// ---------------------------------------------------------------------------
__global__ void __launch_bounds__(256)
build_table_kernel(const float* __restrict__ W, const float* __restrict__ b) {
    __shared__ float sSin[NPB][64];
    __shared__ float sCos[NPB][64];
    __shared__ float sF[64];
    __shared__ float sR0[NPB][H];
    __shared__ float sR1[NPB][H];

    const int tid   = threadIdx.x;
    const int o     = tid & (H - 1);
    const int half  = tid >> 7;
    const int node0 = blockIdx.x * NPB;

    if (tid < 64) sF[tid] = expf(FREQ_DECAY * (float)tid);

#pragma unroll
    for (int e = tid; e < NPB * 64; e += 256) {
        int ni = e >> 6;
        int j  = e & 63;
        float q = (float)(node0 + ni) * DELTA;
        float f = expf(FREQ_DECAY * (float)j);
        float s, c;
        sincosf(q * f, &s, &c);
        sSin[ni][j] = s;
        sCos[ni][j] = c;
    }

    float4 wreg[16];
    {
        const float4* wrow =
            reinterpret_cast<const float4*>(W + (size_t)o * H + 64 * half);
#pragma unroll
        for (int i = 0; i < 16; i++) wreg[i] = wrow[i];
    }

    float g0[NPB], g1[NPB];
    const float binit = (half == 0) ? b[o] : 0.0f;
#pragma unroll
    for (int ni = 0; ni < NPB; ni++) { g0[ni] = binit; g1[ni] = 0.0f; }

    __syncthreads();

#pragma unroll
    for (int ni = 0; ni < NPB; ni++) {
#pragma unroll
        for (int i = 0; i < 16; i++) {
            int j0 = 32 * half + 2 * i;
            float s0 = sSin[ni][j0],     c0 = sCos[ni][j0];
            float s1 = sSin[ni][j0 + 1], c1 = sCos[ni][j0 + 1];
            float4 w = wreg[i];
            g0[ni] = fmaf(w.x, s0, g0[ni]);
            g0[ni] = fmaf(w.y, c0, g0[ni]);
            g0[ni] = fmaf(w.z, s1, g0[ni]);
            g0[ni] = fmaf(w.w, c1, g0[ni]);
            g1[ni] = fmaf(sF[j0],     fmaf(w.x, c0, -w.y * s0), g1[ni]);
            g1[ni] = fmaf(sF[j0 + 1], fmaf(w.z, c1, -w.w * s1), g1[ni]);
        }
    }

    if (half == 1) {
#pragma unroll
        for (int ni = 0; ni < NPB; ni++) {
            sR0[ni][o] = g0[ni];
            sR1[ni][o] = g1[ni];
        }
    }
    __syncthreads();
    if (half == 0) {
#pragma unroll
        for (int ni = 0; ni < NPB; ni++) {
            int node = node0 + ni;
            if (node < NODES) {
                float a0 = g0[ni] + sR0[ni][o];
                float a1 = g1[ni] + sR1[ni][o];
                g_T[node][o] =
                    __halves2half2(__float2half_rn(a0), __float2half_rn(a1));
            }
        }
    }
}

// ---------------------------------------------------------------------------
// Main kernel (measured-best, unchanged except the clamp constant):
// tile-blocked, all-sequential stores, k/delta dedup.
// Grid = 32x32 tile-pairs x 4 row-groups = 4096 blocks of 256 threads.
// The (n-tile x m-tile) blocking is load-bearing: all 8 warps iterate the
// SAME 32-point m-tile, so table lines for the block's k-values are heavily
// reused in L1 (the R14 contiguous-footprint remap broke this: 78 -> 117 us).
// Phase A: one unique (n-row, m) pair per thread -> (k, delta) in smem.
// Phase B: warp w streams n-row grp*8+w against the m-tile: per m a broadcast
// LDS, one uint4 table load (512 B/warp, L2-hot; table now 512 KB), 4 FMAs,
// one streaming STG.128 -> every warp writes a 16 KB fully sequential run.
// ---------------------------------------------------------------------------
__global__ void __launch_bounds__(256)
geo_emb_kernel(const float* __restrict__ pts, float* __restrict__ out) {
    __shared__ int   sk[256];
    __shared__ float sd[256];

    const int tid  = threadIdx.x;
    const int pair = blockIdx.x >> 2;     // 0..1023: (ti, tj) ordered
    const int grp  = blockIdx.x & 3;
    const int ti   = pair >> 5;
    const int tj   = pair & 31;

    // Phase A: one unique pair per thread -> (k, delta) in smem.
    {
        const int nl = tid >> 5;          // 0..7
        const int ml = tid & 31;
        const int n  = ti * TILE + grp * RROWS + nl;
        const int m  = tj * TILE + ml;
        float dx = pts[n * 3 + 0] - pts[m * 3 + 0];
        float dy = pts[n * 3 + 1] - pts[m * 3 + 1];
        float dz = pts[n * 3 + 2] - pts[m * 3 + 2];
        float d  = sqrtf(fmaf(dx, dx, fmaf(dy, dy, dz * dz))) * 5.0f;
        int k = __float2int_rn(d * INV_DELTA);
        k = min(k, NODES - 1);
        sk[tid] = k;
        sd[tid] = fmaf((float)k, -DELTA, d);   // in [-DELTA/2, DELTA/2]
    }
    __syncthreads();

    // Phase B: stream one n-row per warp, all stores sequential.
    const int w    = tid >> 5;
    const int lane = tid & 31;
    const int n    = ti * TILE + grp * RROWS + w;
    float* rowN = out + ((size_t)n * NPTS + (size_t)tj * TILE) * H + 4 * lane;

#pragma unroll 8
    for (int ml = 0; ml < TILE; ml++) {
        int   k     = sk[w * 32 + ml];    // broadcast LDS (no conflicts)
        float delta = sd[w * 32 + ml];

        const uint4 t = *(reinterpret_cast<const uint4*>(&g_T[k][0]) + lane);
        float2 p0 = __half22float2(*reinterpret_cast<const __half2*>(&t.x));
        float2 p1 = __half22float2(*reinterpret_cast<const __half2*>(&t.y));
        float2 p2 = __half22float2(*reinterpret_cast<const __half2*>(&t.z));
        float2 p3 = __half22float2(*reinterpret_cast<const __half2*>(&t.w));

        float4 rr;
        rr.x = fmaf(delta, p0.y, p0.x);
        rr.y = fmaf(delta, p1.y, p1.x);
        rr.z = fmaf(delta, p2.y, p2.x);
        rr.w = fmaf(delta, p3.y, p3.x);

        __stcs(reinterpret_cast<float4*>(rowN + (size_t)ml * H), rr);
    }
}

// ---------------------------------------------------------------------------
// Inputs: points (1,1024,3) f32, W (128,128) f32, b (128,) f32.
// Output: (1,1024,1024,128) f32.
// ---------------------------------------------------------------------------
extern "C" void kernel_launch(void* const* d_in, const int* in_sizes, int n_in,
                              void* d_out, int out_size) {
    const float* pts = (const float*)d_in[0];
    const float* W   = (const float*)d_in[1];
    const float* b   = (const float*)d_in[2];
    float* out       = (float*)d_out;

    build_table_kernel<<<NODES / NPB, 256>>>(W, b);
    geo_emb_kernel<<<NBLK, 256>>>(pts, out);
}